// round 14
// baseline (speedup 1.0000x reference)
#include <cuda_runtime.h>
#include <cuda_bf16.h>
#include <cuda_fp16.h>
#include <math.h>
#include <stdint.h>

#define BB 2
#define SEQ 2048
#define DIM 1024
#define NH 16
#define HDIM 64
#define MROWS (BB * SEQ)      // 4096
#define MD ((size_t)MROWS * DIM)
#define DD ((size_t)DIM * DIM)

// ---------------------------------------------------------------------------
// Scratch (fp16 single-path pipeline)
// ---------------------------------------------------------------------------
__device__ __half g_af[3 * MROWS * DIM];
__device__ __half g_wf[4 * DIM * DIM];
__device__ __half g_ph[3 * MROWS * DIM];
__device__ __half g_ao[MROWS * DIM];

// ---------------------------------------------------------------------------
// Helpers
// ---------------------------------------------------------------------------
__device__ __forceinline__ uint32_t smem_u32(const void* p) {
    uint32_t a;
    asm("{ .reg .u64 t; cvta.to.shared.u64 t, %1; cvt.u32.u64 %0, t; }"
        : "=r"(a) : "l"(p));
    return a;
}
__device__ __forceinline__ void ldm_x4(uint32_t* r, uint32_t addr) {
    asm volatile("ldmatrix.sync.aligned.m8n8.x4.shared.b16 {%0,%1,%2,%3}, [%4];"
        : "=r"(r[0]), "=r"(r[1]), "=r"(r[2]), "=r"(r[3]) : "r"(addr));
}
__device__ __forceinline__ void ldm_x4t(uint32_t* r, uint32_t addr) {
    asm volatile("ldmatrix.sync.aligned.m8n8.x4.trans.shared.b16 {%0,%1,%2,%3}, [%4];"
        : "=r"(r[0]), "=r"(r[1]), "=r"(r[2]), "=r"(r[3]) : "r"(addr));
}
// fp32-accumulator fp16 MMA
__device__ __forceinline__ void mma_fp16(float* c, const uint32_t* a, const uint32_t* b) {
    asm volatile("mma.sync.aligned.m16n8k16.row.col.f32.f16.f16.f32 "
        "{%0,%1,%2,%3}, {%4,%5,%6,%7}, {%8,%9}, {%0,%1,%2,%3};"
        : "+f"(c[0]), "+f"(c[1]), "+f"(c[2]), "+f"(c[3])
        : "r"(a[0]), "r"(a[1]), "r"(a[2]), "r"(a[3]), "r"(b[0]), "r"(b[1]));
}
// fp16-accumulator fp16 MMA
__device__ __forceinline__ void mma_f16acc(uint32_t* c, const uint32_t* a, const uint32_t* b) {
    asm volatile("mma.sync.aligned.m16n8k16.row.col.f16.f16.f16.f16 "
        "{%0,%1}, {%2,%3,%4,%5}, {%6,%7}, {%0,%1};"
        : "+r"(c[0]), "+r"(c[1])
        : "r"(a[0]), "r"(a[1]), "r"(a[2]), "r"(a[3]), "r"(b[0]), "r"(b[1]));
}
__device__ __forceinline__ uint32_t ex2h2(uint32_t x) {
    uint32_t y;
    asm("ex2.approx.f16x2 %0, %1;" : "=r"(y) : "r"(x));
    return y;
}
#define CP16(dst, src) \
    asm volatile("cp.async.cg.shared.global [%0], [%1], 16;" :: "r"(dst), "l"(src))
#define CP_COMMIT() asm volatile("cp.async.commit_group;" ::: "memory")
#define CP_WAIT0() asm volatile("cp.async.wait_group 0;" ::: "memory")
#define CP_WAIT1() asm volatile("cp.async.wait_group 1;" ::: "memory")

__device__ __forceinline__ uint32_t pack_h2(float a, float b) {
    __half2 H; H.x = __float2half_rn(a); H.y = __float2half_rn(b);
    return *(uint32_t*)&H;
}

// ---------------------------------------------------------------------------
// fp32 -> fp16 convert, 3 inputs in one launch
// ---------------------------------------------------------------------------
__global__ __launch_bounds__(256) void conv_act3_kernel(
    const float* __restrict__ q, const float* __restrict__ k,
    const float* __restrict__ v, __half* __restrict__ outB)
{
    int z = blockIdx.z;
    const float* X = (z == 0) ? q : (z == 1) ? k : v;
    __half* o = outB + (size_t)z * MD;
    size_t i = (size_t)blockIdx.x * 256 + threadIdx.x;
    float4 a = ((const float4*)X)[2 * i];
    float4 b = ((const float4*)X)[2 * i + 1];
    uint4 r;
    r.x = pack_h2(a.x, a.y);
    r.y = pack_h2(a.z, a.w);
    r.z = pack_h2(b.x, b.y);
    r.w = pack_h2(b.z, b.w);
    ((uint4*)o)[i] = r;
}

// ---------------------------------------------------------------------------
// Weight transpose + fp16 convert, 4 weights in one launch
// ---------------------------------------------------------------------------
__global__ __launch_bounds__(256) void conv_wt4_kernel(
    const float* __restrict__ Wq, const float* __restrict__ Wk,
    const float* __restrict__ Wv, const float* __restrict__ Wo,
    __half* __restrict__ outB)
{
    __shared__ float tile[32][33];
    int z = blockIdx.z;
    const float* W = (z == 0) ? Wq : (z == 1) ? Wk : (z == 2) ? Wv : Wo;
    __half* oT = outB + (size_t)z * DD;
    int n0 = blockIdx.x * 32, k0 = blockIdx.y * 32;
    int tx = threadIdx.x, ty = threadIdx.y;
#pragma unroll
    for (int j = ty; j < 32; j += 8)
        tile[j][tx] = W[(size_t)(k0 + j) * DIM + n0 + tx];
    __syncthreads();
#pragma unroll
    for (int j = ty; j < 32; j += 8)
        oT[(size_t)(n0 + j) * DIM + k0 + tx] = __float2half_rn(tile[tx][j]);
}

// ---------------------------------------------------------------------------
// fp16 GEMM v7: R10 shape (128x128 CTA, 4 warps 2m x 2n, warp 64x64, BK=64,
// 3-stage cp.async, one sync/chunk, 2 CTAs/SM) BUT with f16 chunk
// accumulators (K=64 chains, rt 8 vs 16) flushed to fp32 once per chunk.
// Flush = 256 FMA-pipe ops/warp/chunk -> 50% FMA duty, tensor still limits.
// ---------------------------------------------------------------------------
#define GPITCH 144
#define GT_BYTES (128 * GPITCH)          // 18432
#define GSTAGE (2 * GT_BYTES)            // 36864
#define GSMEM  (3 * GSTAGE)              // 110592

__device__ __forceinline__ void g_load(uint32_t dst, const __half* __restrict__ src,
                                       int row0, int k0, int t)
{
#pragma unroll
    for (int i = 0; i < 8; i++) {
        int idx = i * 128 + t;
        int r = idx >> 3, seg = (idx & 7) << 4;
        uint32_t d = dst + (uint32_t)(r * GPITCH + seg);
        const char* s = (const char*)(src + (size_t)(row0 + r) * DIM + k0) + seg;
        CP16(d, s);
    }
}

__global__ __launch_bounds__(128, 2) void gemm_f16_kernel(
    const __half* __restrict__ AB, const __half* __restrict__ WB,
    const float* __restrict__ b0p, const float* __restrict__ b1p,
    const float* __restrict__ b2p,
    float* __restrict__ Cf, __half* __restrict__ ChB)
{
    extern __shared__ char smraw[];
    uint32_t sb = smem_u32(smraw);
    const int z = blockIdx.z;
    const __half* A = AB + (size_t)z * MD;
    const __half* W = WB + (size_t)z * DD;
    const float* bias = (z == 0) ? b0p : (z == 1) ? b1p : b2p;
    __half* Ch = ChB + (size_t)z * MD;

    const int t = threadIdx.x;
    const int wid = t >> 5, lane = t & 31;
    const int wm = wid >> 1, wn = wid & 1;
    const int m0 = blockIdx.y * 128, n0 = blockIdx.x * 128;

#pragma unroll
    for (int c = 0; c < 2; c++) {
        uint32_t st = sb + c * GSTAGE;
        g_load(st,            A, m0, c * 64, t);
        g_load(st + GT_BYTES, W, n0, c * 64, t);
        CP_COMMIT();
    }

    float facc[4][8][4];
#pragma unroll
    for (int mt = 0; mt < 4; mt++)
#pragma unroll
        for (int nt = 0; nt < 8; nt++)
#pragma unroll
            for (int e = 0; e < 4; e++) facc[mt][nt][e] = 0.f;

    const uint32_t arow_off = (uint32_t)((lane & 15) * GPITCH + (lane >> 4) * 16);
    const uint32_t brow_off = (uint32_t)(((lane & 7) + ((lane >> 4) << 3)) * GPITCH
                                         + (((lane >> 3) & 1) << 4));

#pragma unroll 1
    for (int c = 0; c < 16; c++) {
        if (c + 1 < 16) CP_WAIT1(); else CP_WAIT0();
        __syncthreads();
        uint32_t sa = sb + (c % 3) * GSTAGE;

        // f16 chunk accumulators (K=64 chain per chunk)
        uint32_t hacc[4][8][2];
#pragma unroll
        for (int mt = 0; mt < 4; mt++)
#pragma unroll
            for (int nt = 0; nt < 8; nt++) { hacc[mt][nt][0] = 0u; hacc[mt][nt][1] = 0u; }

#pragma unroll
        for (int ks = 0; ks < 4; ks++) {
            uint32_t ah[4][4], bh[4][4];
#pragma unroll
            for (int mt = 0; mt < 4; mt++) {
                uint32_t off = (uint32_t)((wm * 64 + mt * 16) * GPITCH + ks * 32)
                               + arow_off;
                ldm_x4(ah[mt], sa + off);
            }
#pragma unroll
            for (int np = 0; np < 4; np++) {
                uint32_t off = (uint32_t)((wn * 64 + np * 16) * GPITCH + ks * 32)
                               + brow_off;
                ldm_x4(bh[np], sa + GT_BYTES + off);
            }
#pragma unroll
            for (int mt = 0; mt < 4; mt++)
#pragma unroll
                for (int nt = 0; nt < 8; nt++)
                    mma_f16acc(hacc[mt][nt], ah[mt], &bh[nt >> 1][(nt & 1) * 2]);
        }

        // flush chunk sums to fp32 masters (FMA pipe, overlaps next chunk's
        // tensor work from the other warp on this SMSP)
#pragma unroll
        for (int mt = 0; mt < 4; mt++)
#pragma unroll
            for (int nt = 0; nt < 8; nt++) {
                float2 f0 = __half22float2(*(__half2*)&hacc[mt][nt][0]);
                float2 f1 = __half22float2(*(__half2*)&hacc[mt][nt][1]);
                facc[mt][nt][0] += f0.x;
                facc[mt][nt][1] += f0.y;
                facc[mt][nt][2] += f1.x;
                facc[mt][nt][3] += f1.y;
            }

        if (c + 2 < 16) {
            uint32_t st = sb + ((c + 2) % 3) * GSTAGE;
            g_load(st,            A, m0, (c + 2) * 64, t);
            g_load(st + GT_BYTES, W, n0, (c + 2) * 64, t);
            CP_COMMIT();
        }
    }

    const int gid = lane >> 2, tg = lane & 3;
#pragma unroll
    for (int nt = 0; nt < 8; nt++) {
        int c0 = n0 + wn * 64 + nt * 8 + tg * 2;
        float b0 = __ldg(bias + c0), b1 = __ldg(bias + c0 + 1);
#pragma unroll
        for (int mt = 0; mt < 4; mt++) {
            int r0 = m0 + wm * 64 + mt * 16 + gid;
            float v00 = facc[mt][nt][0] + b0, v01 = facc[mt][nt][1] + b1;
            float v10 = facc[mt][nt][2] + b0, v11 = facc[mt][nt][3] + b1;
            if (Cf) {
                *(float2*)(Cf + (size_t)r0 * DIM + c0) = make_float2(v00, v01);
                *(float2*)(Cf + (size_t)(r0 + 8) * DIM + c0) = make_float2(v10, v11);
            } else {
                *(uint32_t*)(Ch + (size_t)r0 * DIM + c0) = pack_h2(v00, v01);
                *(uint32_t*)(Ch + (size_t)(r0 + 8) * DIM + c0) = pack_h2(v10, v11);
            }
        }
    }
}

// ---------------------------------------------------------------------------
// Flash attention v7 (R10 verbatim): 4 warps x 32 q-rows, 128 threads,
// 2 CTAs/SM, f16-acc S, ks-outer loops, 3-stage pipeline, 1 sync/iter.
// ---------------------------------------------------------------------------
#define FT_BYTES (64 * 144)              // 9216
#define FQ_BYTES (128 * 144)             // 18432
#define FSTAGE   (2 * FT_BYTES + 256)    // 18688
#define FSMEM    (FQ_BYTES + 3 * FSTAGE) // 74496

#define FSCALE 0.18033688f          // 0.125 * log2(e)
#define FMASKC (-1.44269504e12f)    // -1e12 * log2(e); saturates to -inf in fp16

__device__ __forceinline__ void f_load128(uint32_t dst, const __half* __restrict__ src,
                                          int t)
{
#pragma unroll
    for (int i = 0; i < 8; i++) {
        int idx = i * 128 + t;
        int r = idx >> 3, c = (idx & 7) << 4;
        CP16(dst + (uint32_t)(r * 144 + c), (const char*)(src + (size_t)r * DIM) + c);
    }
}
__device__ __forceinline__ void f_load64(uint32_t dst, const __half* __restrict__ src,
                                         int t)
{
#pragma unroll
    for (int i = 0; i < 4; i++) {
        int idx = i * 128 + t;
        int r = idx >> 3, c = (idx & 7) << 4;
        CP16(dst + (uint32_t)(r * 144 + c), (const char*)(src + (size_t)r * DIM) + c);
    }
}

__global__ __launch_bounds__(128, 2) void flash7_kernel(
    const __half* __restrict__ QhB, const float* __restrict__ mask,
    __half* __restrict__ Oh)
{
    extern __shared__ char smraw[];
    uint32_t sb = smem_u32(smraw);
    const int qt = blockIdx.x, h = blockIdx.y, b = blockIdx.z;
    const int t = threadIdx.x;
    const int w = t >> 5, lane = t & 31;
    const int gid = lane >> 2, tg = lane & 3;

    const size_t headoff = (size_t)h * HDIM;
    const __half* Qh0 = QhB + ((size_t)(b * SEQ + qt * 128)) * DIM + headoff;
    const __half* Kh0 = QhB + MD + ((size_t)(b * SEQ)) * DIM + headoff;
    const __half* Vh0 = QhB + 2 * MD + ((size_t)(b * SEQ)) * DIM + headoff;
    const float* mrow = mask + (size_t)b * SEQ;

    f_load128(sb, Qh0, t);
#pragma unroll
    for (int c = 0; c < 2; c++) {
        uint32_t st = sb + FQ_BYTES + c * FSTAGE;
        f_load64(st, Kh0 + (size_t)(c * 64) * DIM, t);
        f_load64(st + FT_BYTES, Vh0 + (size_t)(c * 64) * DIM, t);
        if (t < 16) CP16(st + 2 * FT_BYTES + t * 16, mrow + c * 64 + t * 4);
        CP_COMMIT();
    }
    CP_WAIT1();
    __syncthreads();

    uint32_t qh[2][4][4];
    {
        const uint32_t arow_off = (uint32_t)((lane & 15) * 144 + (lane >> 4) * 16);
#pragma unroll
        for (int mt = 0; mt < 2; mt++)
#pragma unroll
            for (int ks = 0; ks < 4; ks++)
                ldm_x4(qh[mt][ks],
                       sb + (uint32_t)((w * 32 + mt * 16) * 144 + ks * 32) + arow_off);
    }

    float o_[2][8][4];
#pragma unroll
    for (int mt = 0; mt < 2; mt++)
#pragma unroll
        for (int j = 0; j < 8; j++)
#pragma unroll
            for (int e = 0; e < 4; e++) o_[mt][j][e] = 0.f;
    float li[4] = {0.f, 0.f, 0.f, 0.f};

    const __half2 fs2 = __float2half2_rn(FSCALE);
    const uint32_t krow_off = (uint32_t)((((lane >> 4) << 3) + (lane & 7)) * 144
                                         + (((lane >> 3) & 1) << 4));
    const uint32_t vrow_off = (uint32_t)(((((lane >> 3) & 1) << 3) + (lane & 7)) * 144
                                         + ((lane >> 4) << 4));

#pragma unroll 1
    for (int kt = 0; kt < 32; kt++) {
        if (kt >= 30) CP_WAIT0(); else CP_WAIT1();
        __syncthreads();
        uint32_t stb = sb + FQ_BYTES + (kt % 3) * FSTAGE;
        const float* smask = (const float*)(smraw + FQ_BYTES + (kt % 3) * FSTAGE
                                            + 2 * FT_BYTES);

        uint32_t mvu[8];
#pragma unroll
        for (int j = 0; j < 8; j++)
            mvu[j] = pack_h2(smask[j * 8 + tg * 2] * FMASKC,
                             smask[j * 8 + tg * 2 + 1] * FMASKC);

        uint32_t sh[2][8][2];
#pragma unroll
        for (int mt = 0; mt < 2; mt++)
#pragma unroll
            for (int j = 0; j < 8; j++) { sh[mt][j][0] = 0u; sh[mt][j][1] = 0u; }

#pragma unroll
        for (int ks = 0; ks < 4; ks++) {
#pragma unroll
            for (int jp = 0; jp < 4; jp++) {
                uint32_t k4[4];
                ldm_x4(k4, stb + (uint32_t)(jp * 16 * 144 + ks * 32) + krow_off);
#pragma unroll
                for (int mt = 0; mt < 2; mt++) {
                    mma_f16acc(sh[mt][2 * jp],     qh[mt][ks], k4);
                    mma_f16acc(sh[mt][2 * jp + 1], qh[mt][ks], k4 + 2);
                }
            }
        }

        uint32_t pah[2][4][4];
#pragma unroll
        for (int mt = 0; mt < 2; mt++) {
            __half2 racc0 = __float2half2_rn(0.f), racc1 = __float2half2_rn(0.f);
#pragma unroll
            for (int j = 0; j < 8; j++) {
                __half2 x01 = __hfma2(*(__half2*)&sh[mt][j][0], fs2, *(__half2*)&mvu[j]);
                __half2 x23 = __hfma2(*(__half2*)&sh[mt][j][1], fs2, *(__half2*)&mvu[j]);
                uint32_t p01 = ex2h2(*(uint32_t*)&x01);
                uint32_t p23 = ex2h2(*(uint32_t*)&x23);
                int ks = j >> 1, half = (j & 1) << 1;
                pah[mt][ks][half + 0] = p01;
                pah[mt][ks][half + 1] = p23;
                racc0 = __hadd2(racc0, *(__half2*)&p01);
                racc1 = __hadd2(racc1, *(__half2*)&p23);
            }
            float2 f0 = __half22float2(racc0);
            float2 f1 = __half22float2(racc1);
            float rs0 = f0.x + f0.y, rs1 = f1.x + f1.y;
            rs0 += __shfl_xor_sync(0xffffffffu, rs0, 1);
            rs0 += __shfl_xor_sync(0xffffffffu, rs0, 2);
            rs1 += __shfl_xor_sync(0xffffffffu, rs1, 1);
            rs1 += __shfl_xor_sync(0xffffffffu, rs1, 2);
            li[2 * mt] += rs0;
            li[2 * mt + 1] += rs1;
        }

#pragma unroll
        for (int ks = 0; ks < 4; ks++) {
#pragma unroll
            for (int jp = 0; jp < 4; jp++) {
                uint32_t v4[4];
                ldm_x4t(v4, stb + FT_BYTES
                        + (uint32_t)(ks * 16 * 144 + jp * 32) + vrow_off);
#pragma unroll
                for (int mt = 0; mt < 2; mt++) {
                    mma_fp16(o_[mt][2 * jp],     pah[mt][ks], v4);
                    mma_fp16(o_[mt][2 * jp + 1], pah[mt][ks], v4 + 2);
                }
            }
        }

        if (kt + 2 < 32) {
            uint32_t st2 = sb + FQ_BYTES + ((kt + 2) % 3) * FSTAGE;
            size_t roff = (size_t)((kt + 2) * 64) * DIM;
            f_load64(st2, Kh0 + roff, t);
            f_load64(st2 + FT_BYTES, Vh0 + roff, t);
            if (t < 16) CP16(st2 + 2 * FT_BYTES + t * 16, mrow + (kt + 2) * 64 + t * 4);
            CP_COMMIT();
        }
    }

#pragma unroll
    for (int mt = 0; mt < 2; mt++) {
        float inv0 = 1.f / li[2 * mt], inv1 = 1.f / li[2 * mt + 1];
        size_t r0 = ((size_t)(b * SEQ + qt * 128 + w * 32 + mt * 16 + gid)) * DIM
                    + headoff;
        size_t r1 = r0 + (size_t)8 * DIM;
#pragma unroll
        for (int j = 0; j < 8; j++) {
            int col = j * 8 + tg * 2;
            *(uint32_t*)(Oh + r0 + col) = pack_h2(o_[mt][j][0] * inv0,
                                                  o_[mt][j][1] * inv0);
            *(uint32_t*)(Oh + r1 + col) = pack_h2(o_[mt][j][2] * inv1,
                                                  o_[mt][j][3] * inv1);
        }
    }
}

// ---------------------------------------------------------------------------
// Launch
// ---------------------------------------------------------------------------
extern "C" void kernel_launch(void* const* d_in, const int* in_sizes, int n_in,
                              void* d_out, int out_size)
{
    const float* q    = (const float*)d_in[0];
    const float* k    = (const float*)d_in[1];
    const float* v    = (const float*)d_in[2];
    const float* mask = (const float*)d_in[3];
    const float* Wq   = (const float*)d_in[4];
    const float* bq   = (const float*)d_in[5];
    const float* Wk   = (const float*)d_in[6];
    const float* bk   = (const float*)d_in[7];
    const float* Wv   = (const float*)d_in[8];
    const float* bv   = (const float*)d_in[9];
    const float* Wo   = (const float*)d_in[10];
    const float* bo   = (const float*)d_in[11];
    float* out = (float*)d_out;

    __half *af, *wf, *ph, *ao;
    cudaGetSymbolAddress((void**)&af, g_af);
    cudaGetSymbolAddress((void**)&wf, g_wf);
    cudaGetSymbolAddress((void**)&ph, g_ph);
    cudaGetSymbolAddress((void**)&ao, g_ao);

    cudaFuncSetAttribute(gemm_f16_kernel,
                         cudaFuncAttributeMaxDynamicSharedMemorySize, GSMEM);
    cudaFuncSetAttribute(flash7_kernel,
                         cudaFuncAttributeMaxDynamicSharedMemorySize, FSMEM);

    conv_act3_kernel<<<dim3(MD / 8 / 256, 1, 3), 256>>>(q, k, v, af);
    conv_wt4_kernel<<<dim3(32, 32, 4), dim3(32, 8)>>>(Wq, Wk, Wv, Wo, wf);

    // QKV projections (batched) -> fp16
    gemm_f16_kernel<<<dim3(DIM / 128, MROWS / 128, 3), 128, GSMEM>>>(
        af, wf, bq, bk, bv, nullptr, ph);

    // attention -> fp16
    flash7_kernel<<<dim3(SEQ / 128, NH, BB), 128, FSMEM>>>(ph, mask, ao);

    // O projection -> fp32 out
    gemm_f16_kernel<<<dim3(DIM / 128, MROWS / 128, 1), 128, GSMEM>>>(
        ao, wf + 3 * DD, bo, bo, bo, out, nullptr);
}

// round 15
// speedup vs baseline: 1.0833x; 1.0833x over previous
#include <cuda_runtime.h>
#include <cuda_bf16.h>
#include <cuda_fp16.h>
#include <math.h>
#include <stdint.h>

#define BB 2
#define SEQ 2048
#define DIM 1024
#define NH 16
#define HDIM 64
#define MROWS (BB * SEQ)      // 4096
#define MD ((size_t)MROWS * DIM)
#define DD ((size_t)DIM * DIM)

// ---------------------------------------------------------------------------
// Scratch (fp16 single-path pipeline)
// ---------------------------------------------------------------------------
__device__ __half g_af[3 * MROWS * DIM];
__device__ __half g_wf[4 * DIM * DIM];
__device__ __half g_ph[3 * MROWS * DIM];
__device__ __half g_ao[MROWS * DIM];

// ---------------------------------------------------------------------------
// Helpers
// ---------------------------------------------------------------------------
__device__ __forceinline__ uint32_t smem_u32(const void* p) {
    uint32_t a;
    asm("{ .reg .u64 t; cvta.to.shared.u64 t, %1; cvt.u32.u64 %0, t; }"
        : "=r"(a) : "l"(p));
    return a;
}
__device__ __forceinline__ void ldm_x4(uint32_t* r, uint32_t addr) {
    asm volatile("ldmatrix.sync.aligned.m8n8.x4.shared.b16 {%0,%1,%2,%3}, [%4];"
        : "=r"(r[0]), "=r"(r[1]), "=r"(r[2]), "=r"(r[3]) : "r"(addr));
}
__device__ __forceinline__ void ldm_x4t(uint32_t* r, uint32_t addr) {
    asm volatile("ldmatrix.sync.aligned.m8n8.x4.trans.shared.b16 {%0,%1,%2,%3}, [%4];"
        : "=r"(r[0]), "=r"(r[1]), "=r"(r[2]), "=r"(r[3]) : "r"(addr));
}
// fp32-accumulator fp16 MMA
__device__ __forceinline__ void mma_fp16(float* c, const uint32_t* a, const uint32_t* b) {
    asm volatile("mma.sync.aligned.m16n8k16.row.col.f32.f16.f16.f32 "
        "{%0,%1,%2,%3}, {%4,%5,%6,%7}, {%8,%9}, {%0,%1,%2,%3};"
        : "+f"(c[0]), "+f"(c[1]), "+f"(c[2]), "+f"(c[3])
        : "r"(a[0]), "r"(a[1]), "r"(a[2]), "r"(a[3]), "r"(b[0]), "r"(b[1]));
}
// fp16-accumulator fp16 MMA (for S)
__device__ __forceinline__ void mma_f16acc(uint32_t* c, const uint32_t* a, const uint32_t* b) {
    asm volatile("mma.sync.aligned.m16n8k16.row.col.f16.f16.f16.f16 "
        "{%0,%1}, {%2,%3,%4,%5}, {%6,%7}, {%0,%1};"
        : "+r"(c[0]), "+r"(c[1])
        : "r"(a[0]), "r"(a[1]), "r"(a[2]), "r"(a[3]), "r"(b[0]), "r"(b[1]));
}
__device__ __forceinline__ uint32_t ex2h2(uint32_t x) {
    uint32_t y;
    asm("ex2.approx.f16x2 %0, %1;" : "=r"(y) : "r"(x));
    return y;
}
#define CP16(dst, src) \
    asm volatile("cp.async.cg.shared.global [%0], [%1], 16;" :: "r"(dst), "l"(src))
#define CP_COMMIT() asm volatile("cp.async.commit_group;" ::: "memory")
#define CP_WAIT0() asm volatile("cp.async.wait_group 0;" ::: "memory")
#define CP_WAIT1() asm volatile("cp.async.wait_group 1;" ::: "memory")

__device__ __forceinline__ uint32_t pack_h2(float a, float b) {
    __half2 H; H.x = __float2half_rn(a); H.y = __float2half_rn(b);
    return *(uint32_t*)&H;
}

// ---------------------------------------------------------------------------
// fp32 -> fp16 convert, 3 inputs in one launch
// ---------------------------------------------------------------------------
__global__ __launch_bounds__(256) void conv_act3_kernel(
    const float* __restrict__ q, const float* __restrict__ k,
    const float* __restrict__ v, __half* __restrict__ outB)
{
    int z = blockIdx.z;
    const float* X = (z == 0) ? q : (z == 1) ? k : v;
    __half* o = outB + (size_t)z * MD;
    size_t i = (size_t)blockIdx.x * 256 + threadIdx.x;
    float4 a = ((const float4*)X)[2 * i];
    float4 b = ((const float4*)X)[2 * i + 1];
    uint4 r;
    r.x = pack_h2(a.x, a.y);
    r.y = pack_h2(a.z, a.w);
    r.z = pack_h2(b.x, b.y);
    r.w = pack_h2(b.z, b.w);
    ((uint4*)o)[i] = r;
}

// ---------------------------------------------------------------------------
// Weight transpose + fp16 convert, 4 weights in one launch
// ---------------------------------------------------------------------------
__global__ __launch_bounds__(256) void conv_wt4_kernel(
    const float* __restrict__ Wq, const float* __restrict__ Wk,
    const float* __restrict__ Wv, const float* __restrict__ Wo,
    __half* __restrict__ outB)
{
    __shared__ float tile[32][33];
    int z = blockIdx.z;
    const float* W = (z == 0) ? Wq : (z == 1) ? Wk : (z == 2) ? Wv : Wo;
    __half* oT = outB + (size_t)z * DD;
    int n0 = blockIdx.x * 32, k0 = blockIdx.y * 32;
    int tx = threadIdx.x, ty = threadIdx.y;
#pragma unroll
    for (int j = ty; j < 32; j += 8)
        tile[j][tx] = W[(size_t)(k0 + j) * DIM + n0 + tx];
    __syncthreads();
#pragma unroll
    for (int j = ty; j < 32; j += 8)
        oT[(size_t)(n0 + j) * DIM + k0 + tx] = __float2half_rn(tile[tx][j]);
}

// ---------------------------------------------------------------------------
// fp16 GEMM v5 (R10 config, proven): 128x128 CTA, 4 warps (2m x 2n),
// warp 64x64, BK=64, 3-stage cp.async, one sync/chunk, fp32 acc, 2 CTAs/SM.
// ---------------------------------------------------------------------------
#define GPITCH 144
#define GT_BYTES (128 * GPITCH)          // 18432
#define GSTAGE (2 * GT_BYTES)            // 36864
#define GSMEM  (3 * GSTAGE)              // 110592

__device__ __forceinline__ void g_load(uint32_t dst, const __half* __restrict__ src,
                                       int row0, int k0, int t)
{
#pragma unroll
    for (int i = 0; i < 8; i++) {
        int idx = i * 128 + t;
        int r = idx >> 3, seg = (idx & 7) << 4;
        uint32_t d = dst + (uint32_t)(r * GPITCH + seg);
        const char* s = (const char*)(src + (size_t)(row0 + r) * DIM + k0) + seg;
        CP16(d, s);
    }
}

__global__ __launch_bounds__(128, 2) void gemm_f16_kernel(
    const __half* __restrict__ AB, const __half* __restrict__ WB,
    const float* __restrict__ b0p, const float* __restrict__ b1p,
    const float* __restrict__ b2p,
    float* __restrict__ Cf, __half* __restrict__ ChB)
{
    extern __shared__ char smraw[];
    uint32_t sb = smem_u32(smraw);
    const int z = blockIdx.z;
    const __half* A = AB + (size_t)z * MD;
    const __half* W = WB + (size_t)z * DD;
    const float* bias = (z == 0) ? b0p : (z == 1) ? b1p : b2p;
    __half* Ch = ChB + (size_t)z * MD;

    const int t = threadIdx.x;
    const int wid = t >> 5, lane = t & 31;
    const int wm = wid >> 1, wn = wid & 1;
    const int m0 = blockIdx.y * 128, n0 = blockIdx.x * 128;

#pragma unroll
    for (int c = 0; c < 2; c++) {
        uint32_t st = sb + c * GSTAGE;
        g_load(st,            A, m0, c * 64, t);
        g_load(st + GT_BYTES, W, n0, c * 64, t);
        CP_COMMIT();
    }

    float acc[4][8][4];
#pragma unroll
    for (int mt = 0; mt < 4; mt++)
#pragma unroll
        for (int nt = 0; nt < 8; nt++)
#pragma unroll
            for (int e = 0; e < 4; e++) acc[mt][nt][e] = 0.f;

    const uint32_t arow_off = (uint32_t)((lane & 15) * GPITCH + (lane >> 4) * 16);
    const uint32_t brow_off = (uint32_t)(((lane & 7) + ((lane >> 4) << 3)) * GPITCH
                                         + (((lane >> 3) & 1) << 4));

#pragma unroll 1
    for (int c = 0; c < 16; c++) {
        if (c + 1 < 16) CP_WAIT1(); else CP_WAIT0();
        __syncthreads();
        uint32_t sa = sb + (c % 3) * GSTAGE;

#pragma unroll
        for (int ks = 0; ks < 4; ks++) {
            uint32_t ah[4][4], bh[4][4];
#pragma unroll
            for (int mt = 0; mt < 4; mt++) {
                uint32_t off = (uint32_t)((wm * 64 + mt * 16) * GPITCH + ks * 32)
                               + arow_off;
                ldm_x4(ah[mt], sa + off);
            }
#pragma unroll
            for (int np = 0; np < 4; np++) {
                uint32_t off = (uint32_t)((wn * 64 + np * 16) * GPITCH + ks * 32)
                               + brow_off;
                ldm_x4(bh[np], sa + GT_BYTES + off);
            }
#pragma unroll
            for (int mt = 0; mt < 4; mt++)
#pragma unroll
                for (int nt = 0; nt < 8; nt++)
                    mma_fp16(acc[mt][nt], ah[mt], &bh[nt >> 1][(nt & 1) * 2]);
        }

        if (c + 2 < 16) {
            uint32_t st = sb + ((c + 2) % 3) * GSTAGE;
            g_load(st,            A, m0, (c + 2) * 64, t);
            g_load(st + GT_BYTES, W, n0, (c + 2) * 64, t);
            CP_COMMIT();
        }
    }

    const int gid = lane >> 2, tg = lane & 3;
#pragma unroll
    for (int nt = 0; nt < 8; nt++) {
        int c0 = n0 + wn * 64 + nt * 8 + tg * 2;
        float b0 = __ldg(bias + c0), b1 = __ldg(bias + c0 + 1);
#pragma unroll
        for (int mt = 0; mt < 4; mt++) {
            int r0 = m0 + wm * 64 + mt * 16 + gid;
            float v00 = acc[mt][nt][0] + b0, v01 = acc[mt][nt][1] + b1;
            float v10 = acc[mt][nt][2] + b0, v11 = acc[mt][nt][3] + b1;
            if (Cf) {
                *(float2*)(Cf + (size_t)r0 * DIM + c0) = make_float2(v00, v01);
                *(float2*)(Cf + (size_t)(r0 + 8) * DIM + c0) = make_float2(v10, v11);
            } else {
                *(uint32_t*)(Ch + (size_t)r0 * DIM + c0) = pack_h2(v00, v01);
                *(uint32_t*)(Ch + (size_t)(r0 + 8) * DIM + c0) = pack_h2(v10, v11);
            }
        }
    }
}

// ---------------------------------------------------------------------------
// Flash attention v10: R10 math with IN-PLACE softmax (p overwrites S frags
// -> pah array eliminated, ~32 fewer registers) and 3 CTAs/SM.
// The PV A-fragment for ks is exactly {sh[2ks][0],sh[2ks][1],
// sh[2ks+1][0],sh[2ks+1][1]} = &sh[mt][2ks][0] (contiguous).
// 4 warps x 32 q-rows, 128 threads, 3-stage pipeline, 1 sync/iter.
// ---------------------------------------------------------------------------
#define FT_BYTES (64 * 144)              // 9216
#define FQ_BYTES (128 * 144)             // 18432
#define FSTAGE   (2 * FT_BYTES + 256)    // 18688
#define FSMEM    (FQ_BYTES + 3 * FSTAGE) // 74496  (x3 CTAs = 218 KB <= 228)

#define FSCALE 0.18033688f          // 0.125 * log2(e)
#define FMASKC (-1.44269504e12f)    // -1e12 * log2(e); saturates to -inf in fp16

__device__ __forceinline__ void f_load128(uint32_t dst, const __half* __restrict__ src,
                                          int t)
{
#pragma unroll
    for (int i = 0; i < 8; i++) {
        int idx = i * 128 + t;
        int r = idx >> 3, c = (idx & 7) << 4;
        CP16(dst + (uint32_t)(r * 144 + c), (const char*)(src + (size_t)r * DIM) + c);
    }
}
__device__ __forceinline__ void f_load64(uint32_t dst, const __half* __restrict__ src,
                                         int t)
{
#pragma unroll
    for (int i = 0; i < 4; i++) {
        int idx = i * 128 + t;
        int r = idx >> 3, c = (idx & 7) << 4;
        CP16(dst + (uint32_t)(r * 144 + c), (const char*)(src + (size_t)r * DIM) + c);
    }
}

__global__ __launch_bounds__(128, 3) void flash10_kernel(
    const __half* __restrict__ QhB, const float* __restrict__ mask,
    __half* __restrict__ Oh)
{
    extern __shared__ char smraw[];
    uint32_t sb = smem_u32(smraw);
    const int qt = blockIdx.x, h = blockIdx.y, b = blockIdx.z;
    const int t = threadIdx.x;
    const int w = t >> 5, lane = t & 31;
    const int gid = lane >> 2, tg = lane & 3;

    const size_t headoff = (size_t)h * HDIM;
    const __half* Qh0 = QhB + ((size_t)(b * SEQ + qt * 128)) * DIM + headoff;
    const __half* Kh0 = QhB + MD + ((size_t)(b * SEQ)) * DIM + headoff;
    const __half* Vh0 = QhB + 2 * MD + ((size_t)(b * SEQ)) * DIM + headoff;
    const float* mrow = mask + (size_t)b * SEQ;

    f_load128(sb, Qh0, t);
#pragma unroll
    for (int c = 0; c < 2; c++) {
        uint32_t st = sb + FQ_BYTES + c * FSTAGE;
        f_load64(st, Kh0 + (size_t)(c * 64) * DIM, t);
        f_load64(st + FT_BYTES, Vh0 + (size_t)(c * 64) * DIM, t);
        if (t < 16) CP16(st + 2 * FT_BYTES + t * 16, mrow + c * 64 + t * 4);
        CP_COMMIT();
    }
    CP_WAIT1();
    __syncthreads();

    uint32_t qh[2][4][4];
    {
        const uint32_t arow_off = (uint32_t)((lane & 15) * 144 + (lane >> 4) * 16);
#pragma unroll
        for (int mt = 0; mt < 2; mt++)
#pragma unroll
            for (int ks = 0; ks < 4; ks++)
                ldm_x4(qh[mt][ks],
                       sb + (uint32_t)((w * 32 + mt * 16) * 144 + ks * 32) + arow_off);
    }

    float o_[2][8][4];
#pragma unroll
    for (int mt = 0; mt < 2; mt++)
#pragma unroll
        for (int j = 0; j < 8; j++)
#pragma unroll
            for (int e = 0; e < 4; e++) o_[mt][j][e] = 0.f;
    float li[4] = {0.f, 0.f, 0.f, 0.f};

    const __half2 fs2 = __float2half2_rn(FSCALE);
    const uint32_t krow_off = (uint32_t)((((lane >> 4) << 3) + (lane & 7)) * 144
                                         + (((lane >> 3) & 1) << 4));
    const uint32_t vrow_off = (uint32_t)(((((lane >> 3) & 1) << 3) + (lane & 7)) * 144
                                         + ((lane >> 4) << 4));

#pragma unroll 1
    for (int kt = 0; kt < 32; kt++) {
        if (kt >= 30) CP_WAIT0(); else CP_WAIT1();
        __syncthreads();
        uint32_t stb = sb + FQ_BYTES + (kt % 3) * FSTAGE;
        const float* smask = (const float*)(smraw + FQ_BYTES + (kt % 3) * FSTAGE
                                            + 2 * FT_BYTES);

        uint32_t mvu[8];
#pragma unroll
        for (int j = 0; j < 8; j++)
            mvu[j] = pack_h2(smask[j * 8 + tg * 2] * FMASKC,
                             smask[j * 8 + tg * 2 + 1] * FMASKC);

        // S = Q @ K^T (f16 accumulators, ks outer)
        uint32_t sh[2][8][2];
#pragma unroll
        for (int mt = 0; mt < 2; mt++)
#pragma unroll
            for (int j = 0; j < 8; j++) { sh[mt][j][0] = 0u; sh[mt][j][1] = 0u; }

#pragma unroll
        for (int ks = 0; ks < 4; ks++) {
#pragma unroll
            for (int jp = 0; jp < 4; jp++) {
                uint32_t k4[4];
                ldm_x4(k4, stb + (uint32_t)(jp * 16 * 144 + ks * 32) + krow_off);
#pragma unroll
                for (int mt = 0; mt < 2; mt++) {
                    mma_f16acc(sh[mt][2 * jp],     qh[mt][ks], k4);
                    mma_f16acc(sh[mt][2 * jp + 1], qh[mt][ks], k4 + 2);
                }
            }
        }

        // softmax in f16x2, IN PLACE (p overwrites sh)
#pragma unroll
        for (int mt = 0; mt < 2; mt++) {
            __half2 racc0 = __float2half2_rn(0.f), racc1 = __float2half2_rn(0.f);
#pragma unroll
            for (int j = 0; j < 8; j++) {
                __half2 x01 = __hfma2(*(__half2*)&sh[mt][j][0], fs2, *(__half2*)&mvu[j]);
                __half2 x23 = __hfma2(*(__half2*)&sh[mt][j][1], fs2, *(__half2*)&mvu[j]);
                sh[mt][j][0] = ex2h2(*(uint32_t*)&x01);
                sh[mt][j][1] = ex2h2(*(uint32_t*)&x23);
                racc0 = __hadd2(racc0, *(__half2*)&sh[mt][j][0]);
                racc1 = __hadd2(racc1, *(__half2*)&sh[mt][j][1]);
            }
            float2 f0 = __half22float2(racc0);
            float2 f1 = __half22float2(racc1);
            float rs0 = f0.x + f0.y, rs1 = f1.x + f1.y;
            rs0 += __shfl_xor_sync(0xffffffffu, rs0, 1);
            rs0 += __shfl_xor_sync(0xffffffffu, rs0, 2);
            rs1 += __shfl_xor_sync(0xffffffffu, rs1, 1);
            rs1 += __shfl_xor_sync(0xffffffffu, rs1, 2);
            li[2 * mt] += rs0;
            li[2 * mt + 1] += rs1;
        }

        // O += P @ V; A-fragment for ks is &sh[mt][2*ks][0] (contiguous 4 regs)
#pragma unroll
        for (int ks = 0; ks < 4; ks++) {
#pragma unroll
            for (int jp = 0; jp < 4; jp++) {
                uint32_t v4[4];
                ldm_x4t(v4, stb + FT_BYTES
                        + (uint32_t)(ks * 16 * 144 + jp * 32) + vrow_off);
#pragma unroll
                for (int mt = 0; mt < 2; mt++) {
                    mma_fp16(o_[mt][2 * jp],     &sh[mt][2 * ks][0], v4);
                    mma_fp16(o_[mt][2 * jp + 1], &sh[mt][2 * ks][0], v4 + 2);
                }
            }
        }

        if (kt + 2 < 32) {
            uint32_t st2 = sb + FQ_BYTES + ((kt + 2) % 3) * FSTAGE;
            size_t roff = (size_t)((kt + 2) * 64) * DIM;
            f_load64(st2, Kh0 + roff, t);
            f_load64(st2 + FT_BYTES, Vh0 + roff, t);
            if (t < 16) CP16(st2 + 2 * FT_BYTES + t * 16, mrow + (kt + 2) * 64 + t * 4);
            CP_COMMIT();
        }
    }

#pragma unroll
    for (int mt = 0; mt < 2; mt++) {
        float inv0 = 1.f / li[2 * mt], inv1 = 1.f / li[2 * mt + 1];
        size_t r0 = ((size_t)(b * SEQ + qt * 128 + w * 32 + mt * 16 + gid)) * DIM
                    + headoff;
        size_t r1 = r0 + (size_t)8 * DIM;
#pragma unroll
        for (int j = 0; j < 8; j++) {
            int col = j * 8 + tg * 2;
            *(uint32_t*)(Oh + r0 + col) = pack_h2(o_[mt][j][0] * inv0,
                                                  o_[mt][j][1] * inv0);
            *(uint32_t*)(Oh + r1 + col) = pack_h2(o_[mt][j][2] * inv1,
                                                  o_[mt][j][3] * inv1);
        }
    }
}

// ---------------------------------------------------------------------------
// Launch
// ---------------------------------------------------------------------------
extern "C" void kernel_launch(void* const* d_in, const int* in_sizes, int n_in,
                              void* d_out, int out_size)
{
    const float* q    = (const float*)d_in[0];
    const float* k    = (const float*)d_in[1];
    const float* v    = (const float*)d_in[2];
    const float* mask = (const float*)d_in[3];
    const float* Wq   = (const float*)d_in[4];
    const float* bq   = (const float*)d_in[5];
    const float* Wk   = (const float*)d_in[6];
    const float* bk   = (const float*)d_in[7];
    const float* Wv   = (const float*)d_in[8];
    const float* bv   = (const float*)d_in[9];
    const float* Wo   = (const float*)d_in[10];
    const float* bo   = (const float*)d_in[11];
    float* out = (float*)d_out;

    __half *af, *wf, *ph, *ao;
    cudaGetSymbolAddress((void**)&af, g_af);
    cudaGetSymbolAddress((void**)&wf, g_wf);
    cudaGetSymbolAddress((void**)&ph, g_ph);
    cudaGetSymbolAddress((void**)&ao, g_ao);

    cudaFuncSetAttribute(gemm_f16_kernel,
                         cudaFuncAttributeMaxDynamicSharedMemorySize, GSMEM);
    cudaFuncSetAttribute(flash10_kernel,
                         cudaFuncAttributeMaxDynamicSharedMemorySize, FSMEM);

    conv_act3_kernel<<<dim3(MD / 8 / 256, 1, 3), 256>>>(q, k, v, af);
    conv_wt4_kernel<<<dim3(32, 32, 4), dim3(32, 8)>>>(Wq, Wk, Wv, Wo, wf);

    // QKV projections (batched) -> fp16
    gemm_f16_kernel<<<dim3(DIM / 128, MROWS / 128, 3), 128, GSMEM>>>(
        af, wf, bq, bk, bv, nullptr, ph);

    // attention -> fp16
    flash10_kernel<<<dim3(SEQ / 128, NH, BB), 128, FSMEM>>>(ph, mask, ao);

    // O projection -> fp32 out
    gemm_f16_kernel<<<dim3(DIM / 128, MROWS / 128, 1), 128, GSMEM>>>(
        ao, wf + 3 * DD, bo, bo, bo, out, nullptr);
}

// round 16
// speedup vs baseline: 1.1004x; 1.0158x over previous
#include <cuda_runtime.h>
#include <cuda_bf16.h>
#include <cuda_fp16.h>
#include <math.h>
#include <stdint.h>

#define BB 2
#define SEQ 2048
#define DIM 1024
#define NH 16
#define HDIM 64
#define MROWS (BB * SEQ)      // 4096
#define MD ((size_t)MROWS * DIM)
#define DD ((size_t)DIM * DIM)

// ---------------------------------------------------------------------------
// Scratch (fp16 single-path pipeline)
// ---------------------------------------------------------------------------
__device__ __half g_af[3 * MROWS * DIM];
__device__ __half g_wf[4 * DIM * DIM];
__device__ __half g_ph[3 * MROWS * DIM];
__device__ __half g_ao[MROWS * DIM];

// ---------------------------------------------------------------------------
// Helpers
// ---------------------------------------------------------------------------
__device__ __forceinline__ uint32_t smem_u32(const void* p) {
    uint32_t a;
    asm("{ .reg .u64 t; cvta.to.shared.u64 t, %1; cvt.u32.u64 %0, t; }"
        : "=r"(a) : "l"(p));
    return a;
}
__device__ __forceinline__ void ldm_x4(uint32_t* r, uint32_t addr) {
    asm volatile("ldmatrix.sync.aligned.m8n8.x4.shared.b16 {%0,%1,%2,%3}, [%4];"
        : "=r"(r[0]), "=r"(r[1]), "=r"(r[2]), "=r"(r[3]) : "r"(addr));
}
__device__ __forceinline__ void ldm_x4t(uint32_t* r, uint32_t addr) {
    asm volatile("ldmatrix.sync.aligned.m8n8.x4.trans.shared.b16 {%0,%1,%2,%3}, [%4];"
        : "=r"(r[0]), "=r"(r[1]), "=r"(r[2]), "=r"(r[3]) : "r"(addr));
}
// fp32-accumulator fp16 MMA
__device__ __forceinline__ void mma_fp16(float* c, const uint32_t* a, const uint32_t* b) {
    asm volatile("mma.sync.aligned.m16n8k16.row.col.f32.f16.f16.f32 "
        "{%0,%1,%2,%3}, {%4,%5,%6,%7}, {%8,%9}, {%0,%1,%2,%3};"
        : "+f"(c[0]), "+f"(c[1]), "+f"(c[2]), "+f"(c[3])
        : "r"(a[0]), "r"(a[1]), "r"(a[2]), "r"(a[3]), "r"(b[0]), "r"(b[1]));
}
// fp16-accumulator fp16 MMA (for S)
__device__ __forceinline__ void mma_f16acc(uint32_t* c, const uint32_t* a, const uint32_t* b) {
    asm volatile("mma.sync.aligned.m16n8k16.row.col.f16.f16.f16.f16 "
        "{%0,%1}, {%2,%3,%4,%5}, {%6,%7}, {%0,%1};"
        : "+r"(c[0]), "+r"(c[1])
        : "r"(a[0]), "r"(a[1]), "r"(a[2]), "r"(a[3]), "r"(b[0]), "r"(b[1]));
}
__device__ __forceinline__ uint32_t ex2h2(uint32_t x) {
    uint32_t y;
    asm("ex2.approx.f16x2 %0, %1;" : "=r"(y) : "r"(x));
    return y;
}
#define CP16(dst, src) \
    asm volatile("cp.async.cg.shared.global [%0], [%1], 16;" :: "r"(dst), "l"(src))
#define CP_COMMIT() asm volatile("cp.async.commit_group;" ::: "memory")
#define CP_WAIT0() asm volatile("cp.async.wait_group 0;" ::: "memory")
#define CP_WAIT1() asm volatile("cp.async.wait_group 1;" ::: "memory")

__device__ __forceinline__ uint32_t pack_h2(float a, float b) {
    __half2 H; H.x = __float2half_rn(a); H.y = __float2half_rn(b);
    return *(uint32_t*)&H;
}

// ---------------------------------------------------------------------------
// fp32 -> fp16 convert, 3 inputs in one launch
// ---------------------------------------------------------------------------
__global__ __launch_bounds__(256) void conv_act3_kernel(
    const float* __restrict__ q, const float* __restrict__ k,
    const float* __restrict__ v, __half* __restrict__ outB)
{
    int z = blockIdx.z;
    const float* X = (z == 0) ? q : (z == 1) ? k : v;
    __half* o = outB + (size_t)z * MD;
    size_t i = (size_t)blockIdx.x * 256 + threadIdx.x;
    float4 a = ((const float4*)X)[2 * i];
    float4 b = ((const float4*)X)[2 * i + 1];
    uint4 r;
    r.x = pack_h2(a.x, a.y);
    r.y = pack_h2(a.z, a.w);
    r.z = pack_h2(b.x, b.y);
    r.w = pack_h2(b.z, b.w);
    ((uint4*)o)[i] = r;
}

// ---------------------------------------------------------------------------
// Weight transpose + fp16 convert, 4 weights in one launch
// ---------------------------------------------------------------------------
__global__ __launch_bounds__(256) void conv_wt4_kernel(
    const float* __restrict__ Wq, const float* __restrict__ Wk,
    const float* __restrict__ Wv, const float* __restrict__ Wo,
    __half* __restrict__ outB)
{
    __shared__ float tile[32][33];
    int z = blockIdx.z;
    const float* W = (z == 0) ? Wq : (z == 1) ? Wk : (z == 2) ? Wv : Wo;
    __half* oT = outB + (size_t)z * DD;
    int n0 = blockIdx.x * 32, k0 = blockIdx.y * 32;
    int tx = threadIdx.x, ty = threadIdx.y;
#pragma unroll
    for (int j = ty; j < 32; j += 8)
        tile[j][tx] = W[(size_t)(k0 + j) * DIM + n0 + tx];
    __syncthreads();
#pragma unroll
    for (int j = ty; j < 32; j += 8)
        oT[(size_t)(n0 + j) * DIM + k0 + tx] = __float2half_rn(tile[tx][j]);
}

// ---------------------------------------------------------------------------
// fp16 GEMM v5 (R10 config, proven): 128x128 CTA, 4 warps (2m x 2n),
// warp 64x64, BK=64, 3-stage cp.async, one sync/chunk, fp32 acc, 2 CTAs/SM.
// ---------------------------------------------------------------------------
#define GPITCH 144
#define GT_BYTES (128 * GPITCH)          // 18432
#define GSTAGE (2 * GT_BYTES)            // 36864
#define GSMEM  (3 * GSTAGE)              // 110592

__device__ __forceinline__ void g_load(uint32_t dst, const __half* __restrict__ src,
                                       int row0, int k0, int t)
{
#pragma unroll
    for (int i = 0; i < 8; i++) {
        int idx = i * 128 + t;
        int r = idx >> 3, seg = (idx & 7) << 4;
        uint32_t d = dst + (uint32_t)(r * GPITCH + seg);
        const char* s = (const char*)(src + (size_t)(row0 + r) * DIM + k0) + seg;
        CP16(d, s);
    }
}

__global__ __launch_bounds__(128, 2) void gemm_f16_kernel(
    const __half* __restrict__ AB, const __half* __restrict__ WB,
    const float* __restrict__ b0p, const float* __restrict__ b1p,
    const float* __restrict__ b2p,
    float* __restrict__ Cf, __half* __restrict__ ChB)
{
    extern __shared__ char smraw[];
    uint32_t sb = smem_u32(smraw);
    const int z = blockIdx.z;
    const __half* A = AB + (size_t)z * MD;
    const __half* W = WB + (size_t)z * DD;
    const float* bias = (z == 0) ? b0p : (z == 1) ? b1p : b2p;
    __half* Ch = ChB + (size_t)z * MD;

    const int t = threadIdx.x;
    const int wid = t >> 5, lane = t & 31;
    const int wm = wid >> 1, wn = wid & 1;
    const int m0 = blockIdx.y * 128, n0 = blockIdx.x * 128;

#pragma unroll
    for (int c = 0; c < 2; c++) {
        uint32_t st = sb + c * GSTAGE;
        g_load(st,            A, m0, c * 64, t);
        g_load(st + GT_BYTES, W, n0, c * 64, t);
        CP_COMMIT();
    }

    float acc[4][8][4];
#pragma unroll
    for (int mt = 0; mt < 4; mt++)
#pragma unroll
        for (int nt = 0; nt < 8; nt++)
#pragma unroll
            for (int e = 0; e < 4; e++) acc[mt][nt][e] = 0.f;

    const uint32_t arow_off = (uint32_t)((lane & 15) * GPITCH + (lane >> 4) * 16);
    const uint32_t brow_off = (uint32_t)(((lane & 7) + ((lane >> 4) << 3)) * GPITCH
                                         + (((lane >> 3) & 1) << 4));

#pragma unroll 1
    for (int c = 0; c < 16; c++) {
        if (c + 1 < 16) CP_WAIT1(); else CP_WAIT0();
        __syncthreads();
        uint32_t sa = sb + (c % 3) * GSTAGE;

#pragma unroll
        for (int ks = 0; ks < 4; ks++) {
            uint32_t ah[4][4], bh[4][4];
#pragma unroll
            for (int mt = 0; mt < 4; mt++) {
                uint32_t off = (uint32_t)((wm * 64 + mt * 16) * GPITCH + ks * 32)
                               + arow_off;
                ldm_x4(ah[mt], sa + off);
            }
#pragma unroll
            for (int np = 0; np < 4; np++) {
                uint32_t off = (uint32_t)((wn * 64 + np * 16) * GPITCH + ks * 32)
                               + brow_off;
                ldm_x4(bh[np], sa + GT_BYTES + off);
            }
#pragma unroll
            for (int mt = 0; mt < 4; mt++)
#pragma unroll
                for (int nt = 0; nt < 8; nt++)
                    mma_fp16(acc[mt][nt], ah[mt], &bh[nt >> 1][(nt & 1) * 2]);
        }

        if (c + 2 < 16) {
            uint32_t st = sb + ((c + 2) % 3) * GSTAGE;
            g_load(st,            A, m0, (c + 2) * 64, t);
            g_load(st + GT_BYTES, W, n0, (c + 2) * 64, t);
            CP_COMMIT();
        }
    }

    const int gid = lane >> 2, tg = lane & 3;
#pragma unroll
    for (int nt = 0; nt < 8; nt++) {
        int c0 = n0 + wn * 64 + nt * 8 + tg * 2;
        float b0 = __ldg(bias + c0), b1 = __ldg(bias + c0 + 1);
#pragma unroll
        for (int mt = 0; mt < 4; mt++) {
            int r0 = m0 + wm * 64 + mt * 16 + gid;
            float v00 = acc[mt][nt][0] + b0, v01 = acc[mt][nt][1] + b1;
            float v10 = acc[mt][nt][2] + b0, v11 = acc[mt][nt][3] + b1;
            if (Cf) {
                *(float2*)(Cf + (size_t)r0 * DIM + c0) = make_float2(v00, v01);
                *(float2*)(Cf + (size_t)(r0 + 8) * DIM + c0) = make_float2(v10, v11);
            } else {
                *(uint32_t*)(Ch + (size_t)r0 * DIM + c0) = pack_h2(v00, v01);
                *(uint32_t*)(Ch + (size_t)(r0 + 8) * DIM + c0) = pack_h2(v10, v11);
            }
        }
    }
}

// ---------------------------------------------------------------------------
// Flash attention v11: R10 pipeline (3 stages, WAIT1 + 1 sync per iter,
// 2 CTAs/SM) with R15's in-place softmax (p overwrites S fragments; PV
// A-fragment for ks is &sh[mt][2*ks][0], contiguous 4 regs). No reg cap.
// 4 warps x 32 q-rows, 128 threads.
// ---------------------------------------------------------------------------
#define FT_BYTES (64 * 144)              // 9216
#define FQ_BYTES (128 * 144)             // 18432
#define FSTAGE   (2 * FT_BYTES + 256)    // 18688
#define FSMEM    (FQ_BYTES + 3 * FSTAGE) // 74496

#define FSCALE 0.18033688f          // 0.125 * log2(e)
#define FMASKC (-1.44269504e12f)    // -1e12 * log2(e); saturates to -inf in fp16

__device__ __forceinline__ void f_load128(uint32_t dst, const __half* __restrict__ src,
                                          int t)
{
#pragma unroll
    for (int i = 0; i < 8; i++) {
        int idx = i * 128 + t;
        int r = idx >> 3, c = (idx & 7) << 4;
        CP16(dst + (uint32_t)(r * 144 + c), (const char*)(src + (size_t)r * DIM) + c);
    }
}
__device__ __forceinline__ void f_load64(uint32_t dst, const __half* __restrict__ src,
                                         int t)
{
#pragma unroll
    for (int i = 0; i < 4; i++) {
        int idx = i * 128 + t;
        int r = idx >> 3, c = (idx & 7) << 4;
        CP16(dst + (uint32_t)(r * 144 + c), (const char*)(src + (size_t)r * DIM) + c);
    }
}

__global__ __launch_bounds__(128, 2) void flash11_kernel(
    const __half* __restrict__ QhB, const float* __restrict__ mask,
    __half* __restrict__ Oh)
{
    extern __shared__ char smraw[];
    uint32_t sb = smem_u32(smraw);
    const int qt = blockIdx.x, h = blockIdx.y, b = blockIdx.z;
    const int t = threadIdx.x;
    const int w = t >> 5, lane = t & 31;
    const int gid = lane >> 2, tg = lane & 3;

    const size_t headoff = (size_t)h * HDIM;
    const __half* Qh0 = QhB + ((size_t)(b * SEQ + qt * 128)) * DIM + headoff;
    const __half* Kh0 = QhB + MD + ((size_t)(b * SEQ)) * DIM + headoff;
    const __half* Vh0 = QhB + 2 * MD + ((size_t)(b * SEQ)) * DIM + headoff;
    const float* mrow = mask + (size_t)b * SEQ;

    f_load128(sb, Qh0, t);
#pragma unroll
    for (int c = 0; c < 2; c++) {
        uint32_t st = sb + FQ_BYTES + c * FSTAGE;
        f_load64(st, Kh0 + (size_t)(c * 64) * DIM, t);
        f_load64(st + FT_BYTES, Vh0 + (size_t)(c * 64) * DIM, t);
        if (t < 16) CP16(st + 2 * FT_BYTES + t * 16, mrow + c * 64 + t * 4);
        CP_COMMIT();
    }
    CP_WAIT1();
    __syncthreads();

    uint32_t qh[2][4][4];
    {
        const uint32_t arow_off = (uint32_t)((lane & 15) * 144 + (lane >> 4) * 16);
#pragma unroll
        for (int mt = 0; mt < 2; mt++)
#pragma unroll
            for (int ks = 0; ks < 4; ks++)
                ldm_x4(qh[mt][ks],
                       sb + (uint32_t)((w * 32 + mt * 16) * 144 + ks * 32) + arow_off);
    }

    float o_[2][8][4];
#pragma unroll
    for (int mt = 0; mt < 2; mt++)
#pragma unroll
        for (int j = 0; j < 8; j++)
#pragma unroll
            for (int e = 0; e < 4; e++) o_[mt][j][e] = 0.f;
    float li[4] = {0.f, 0.f, 0.f, 0.f};

    const __half2 fs2 = __float2half2_rn(FSCALE);
    const uint32_t krow_off = (uint32_t)((((lane >> 4) << 3) + (lane & 7)) * 144
                                         + (((lane >> 3) & 1) << 4));
    const uint32_t vrow_off = (uint32_t)(((((lane >> 3) & 1) << 3) + (lane & 7)) * 144
                                         + ((lane >> 4) << 4));

#pragma unroll 1
    for (int kt = 0; kt < 32; kt++) {
        if (kt >= 30) CP_WAIT0(); else CP_WAIT1();
        __syncthreads();
        uint32_t stb = sb + FQ_BYTES + (kt % 3) * FSTAGE;
        const float* smask = (const float*)(smraw + FQ_BYTES + (kt % 3) * FSTAGE
                                            + 2 * FT_BYTES);

        uint32_t mvu[8];
#pragma unroll
        for (int j = 0; j < 8; j++)
            mvu[j] = pack_h2(smask[j * 8 + tg * 2] * FMASKC,
                             smask[j * 8 + tg * 2 + 1] * FMASKC);

        // S = Q @ K^T (f16 accumulators, ks outer)
        uint32_t sh[2][8][2];
#pragma unroll
        for (int mt = 0; mt < 2; mt++)
#pragma unroll
            for (int j = 0; j < 8; j++) { sh[mt][j][0] = 0u; sh[mt][j][1] = 0u; }

#pragma unroll
        for (int ks = 0; ks < 4; ks++) {
#pragma unroll
            for (int jp = 0; jp < 4; jp++) {
                uint32_t k4[4];
                ldm_x4(k4, stb + (uint32_t)(jp * 16 * 144 + ks * 32) + krow_off);
#pragma unroll
                for (int mt = 0; mt < 2; mt++) {
                    mma_f16acc(sh[mt][2 * jp],     qh[mt][ks], k4);
                    mma_f16acc(sh[mt][2 * jp + 1], qh[mt][ks], k4 + 2);
                }
            }
        }

        // softmax in f16x2, IN PLACE (p overwrites sh)
#pragma unroll
        for (int mt = 0; mt < 2; mt++) {
            __half2 racc0 = __float2half2_rn(0.f), racc1 = __float2half2_rn(0.f);
#pragma unroll
            for (int j = 0; j < 8; j++) {
                __half2 x01 = __hfma2(*(__half2*)&sh[mt][j][0], fs2, *(__half2*)&mvu[j]);
                __half2 x23 = __hfma2(*(__half2*)&sh[mt][j][1], fs2, *(__half2*)&mvu[j]);
                sh[mt][j][0] = ex2h2(*(uint32_t*)&x01);
                sh[mt][j][1] = ex2h2(*(uint32_t*)&x23);
                racc0 = __hadd2(racc0, *(__half2*)&sh[mt][j][0]);
                racc1 = __hadd2(racc1, *(__half2*)&sh[mt][j][1]);
            }
            float2 f0 = __half22float2(racc0);
            float2 f1 = __half22float2(racc1);
            float rs0 = f0.x + f0.y, rs1 = f1.x + f1.y;
            rs0 += __shfl_xor_sync(0xffffffffu, rs0, 1);
            rs0 += __shfl_xor_sync(0xffffffffu, rs0, 2);
            rs1 += __shfl_xor_sync(0xffffffffu, rs1, 1);
            rs1 += __shfl_xor_sync(0xffffffffu, rs1, 2);
            li[2 * mt] += rs0;
            li[2 * mt + 1] += rs1;
        }

        // O += P @ V; A-fragment for ks is &sh[mt][2*ks][0] (contiguous 4 regs)
#pragma unroll
        for (int ks = 0; ks < 4; ks++) {
#pragma unroll
            for (int jp = 0; jp < 4; jp++) {
                uint32_t v4[4];
                ldm_x4t(v4, stb + FT_BYTES
                        + (uint32_t)(ks * 16 * 144 + jp * 32) + vrow_off);
#pragma unroll
                for (int mt = 0; mt < 2; mt++) {
                    mma_fp16(o_[mt][2 * jp],     &sh[mt][2 * ks][0], v4);
                    mma_fp16(o_[mt][2 * jp + 1], &sh[mt][2 * ks][0], v4 + 2);
                }
            }
        }

        if (kt + 2 < 32) {
            uint32_t st2 = sb + FQ_BYTES + ((kt + 2) % 3) * FSTAGE;
            size_t roff = (size_t)((kt + 2) * 64) * DIM;
            f_load64(st2, Kh0 + roff, t);
            f_load64(st2 + FT_BYTES, Vh0 + roff, t);
            if (t < 16) CP16(st2 + 2 * FT_BYTES + t * 16, mrow + (kt + 2) * 64 + t * 4);
            CP_COMMIT();
        }
    }

#pragma unroll
    for (int mt = 0; mt < 2; mt++) {
        float inv0 = 1.f / li[2 * mt], inv1 = 1.f / li[2 * mt + 1];
        size_t r0 = ((size_t)(b * SEQ + qt * 128 + w * 32 + mt * 16 + gid)) * DIM
                    + headoff;
        size_t r1 = r0 + (size_t)8 * DIM;
#pragma unroll
        for (int j = 0; j < 8; j++) {
            int col = j * 8 + tg * 2;
            *(uint32_t*)(Oh + r0 + col) = pack_h2(o_[mt][j][0] * inv0,
                                                  o_[mt][j][1] * inv0);
            *(uint32_t*)(Oh + r1 + col) = pack_h2(o_[mt][j][2] * inv1,
                                                  o_[mt][j][3] * inv1);
        }
    }
}

// ---------------------------------------------------------------------------
// Launch
// ---------------------------------------------------------------------------
extern "C" void kernel_launch(void* const* d_in, const int* in_sizes, int n_in,
                              void* d_out, int out_size)
{
    const float* q    = (const float*)d_in[0];
    const float* k    = (const float*)d_in[1];
    const float* v    = (const float*)d_in[2];
    const float* mask = (const float*)d_in[3];
    const float* Wq   = (const float*)d_in[4];
    const float* bq   = (const float*)d_in[5];
    const float* Wk   = (const float*)d_in[6];
    const float* bk   = (const float*)d_in[7];
    const float* Wv   = (const float*)d_in[8];
    const float* bv   = (const float*)d_in[9];
    const float* Wo   = (const float*)d_in[10];
    const float* bo   = (const float*)d_in[11];
    float* out = (float*)d_out;

    __half *af, *wf, *ph, *ao;
    cudaGetSymbolAddress((void**)&af, g_af);
    cudaGetSymbolAddress((void**)&wf, g_wf);
    cudaGetSymbolAddress((void**)&ph, g_ph);
    cudaGetSymbolAddress((void**)&ao, g_ao);

    cudaFuncSetAttribute(gemm_f16_kernel,
                         cudaFuncAttributeMaxDynamicSharedMemorySize, GSMEM);
    cudaFuncSetAttribute(flash11_kernel,
                         cudaFuncAttributeMaxDynamicSharedMemorySize, FSMEM);

    conv_act3_kernel<<<dim3(MD / 8 / 256, 1, 3), 256>>>(q, k, v, af);
    conv_wt4_kernel<<<dim3(32, 32, 4), dim3(32, 8)>>>(Wq, Wk, Wv, Wo, wf);

    // QKV projections (batched) -> fp16
    gemm_f16_kernel<<<dim3(DIM / 128, MROWS / 128, 3), 128, GSMEM>>>(
        af, wf, bq, bk, bv, nullptr, ph);

    // attention -> fp16
    flash11_kernel<<<dim3(SEQ / 128, NH, BB), 128, FSMEM>>>(ph, mask, ao);

    // O projection -> fp32 out
    gemm_f16_kernel<<<dim3(DIM / 128, MROWS / 128, 1), 128, GSMEM>>>(
        ao, wf + 3 * DD, bo, bo, bo, out, nullptr);
}